// round 15
// baseline (speedup 1.0000x reference)
#include <cuda_runtime.h>
#include <cuda_fp16.h>
#include <cstdint>
#include <math.h>

#define S 2048
#define DMODEL 512
#define NH 8
#define DKH 64
#define WIN 64
#define NEGV -1000000000.0f
#define SD (S*DMODEL)
#define DD (DMODEL*DMODEL)

#define QH_STR 72     // halves per Q/K smem row
#define PA_STR 132    // fp32 words per P row (264 halves)
#define VT_STR 136    // halves per Vt row

#define LDA 40

typedef unsigned int u32;

// ---------------- device scratch (allocation-free rule) ----------------
__device__ __half g_xh[3*SD];     // activations fp16
__device__ __half g_Wh[4*DD];     // weights fp16
__device__ float  g_QKV[3*SD];
__device__ __half g_AOh[SD];      // attention output fp16

// ---------------- fp32 -> fp16 convert ----------------
__global__ void __launch_bounds__(256) convert_fp16(
    const float* __restrict__ q, const float* __restrict__ k, const float* __restrict__ v,
    const float* __restrict__ Wq, const float* __restrict__ Wk,
    const float* __restrict__ Wv, const float* __restrict__ Wo)
{
    const int SD4 = SD/4;
    const int DD4 = DD/4;
    int idx = blockIdx.x * 256 + threadIdx.x;
    const float* src;
    __half* dh;
    if (idx < 3*SD4) {
        int r = idx / SD4;
        size_t e = (size_t)(idx - r*SD4) * 4;
        src = (r == 0 ? q : (r == 1 ? k : v)) + e;
        dh = g_xh + (size_t)r*SD + e;
    } else {
        int j = idx - 3*SD4;
        int r = j / DD4;
        size_t e = (size_t)(j - r*DD4) * 4;
        src = (r == 0 ? Wq : (r == 1 ? Wk : (r == 2 ? Wv : Wo))) + e;
        dh = g_Wh + (size_t)r*DD + e;
    }
    float4 f = *(const float4*)src;
    *(__half2*)(dh)     = __halves2half2(__float2half(f.x), __float2half(f.y));
    *(__half2*)(dh + 2) = __halves2half2(__float2half(f.z), __float2half(f.w));
}

// ---------------- tensor-core helpers ----------------
__device__ __forceinline__ void ldsm4(u32* r, u32 a) {
    asm volatile("ldmatrix.sync.aligned.m8n8.x4.shared.b16 {%0,%1,%2,%3}, [%4];"
        : "=r"(r[0]), "=r"(r[1]), "=r"(r[2]), "=r"(r[3]) : "r"(a));
}
__device__ __forceinline__ void mma_fp16(float* c, const u32* a, const u32* b) {
    asm volatile("mma.sync.aligned.m16n8k16.row.col.f32.f16.f16.f32 "
        "{%0,%1,%2,%3},{%4,%5,%6,%7},{%8,%9},{%0,%1,%2,%3};"
        : "+f"(c[0]), "+f"(c[1]), "+f"(c[2]), "+f"(c[3])
        : "r"(a[0]), "r"(a[1]), "r"(a[2]), "r"(a[3]), "r"(b[0]), "r"(b[1]));
}
__device__ __forceinline__ void cp16(u32 dst, const void* src) {
    asm volatile("cp.async.cg.shared.global [%0], [%1], 16;" :: "r"(dst), "l"(src));
}
__device__ __forceinline__ void cp_commit() {
    asm volatile("cp.async.commit_group;");
}

// ---------------- GEMM: C = A @ W^T (+bias), plain fp16, 64x64 tile ----------------
// splitk==0: blockIdx.z selects (A,W,C) triple; K = 512.
// splitk==1: blockIdx.z selects K-half; epilogue atomicAdds into pre-zeroed C
//            (2 contributions per element -> order-independent, deterministic);
//            bias added by the z==0 split only.
#define STG_T (64*LDA*2)
#define SMEM_GEMM (2*2*STG_T)

__global__ void __launch_bounds__(256, 4) gemm64x64(
    const __half* __restrict__ A_, const __half* __restrict__ W_,
    float* __restrict__ C, const float* __restrict__ bias, int splitk)
{
    extern __shared__ __align__(16) __half dsm[];

    size_t za, zw;
    int kbeg, nst;
    bool addbias;
    if (splitk) {
        za = 0;
        zw = 0;
        kbeg = blockIdx.z * 256;
        nst = 8;
        addbias = (blockIdx.z == 0) && (bias != nullptr);
    } else {
        za = (size_t)blockIdx.z * SD;
        zw = (size_t)blockIdx.z * DD;
        kbeg = 0;
        nst = 16;
        addbias = (bias != nullptr);
    }

    const int tid = threadIdx.x;
    const int m_base = blockIdx.y * 64;
    const int n_base = blockIdx.x * 64;

    const int a_row = tid >> 2;
    const int a_col = (tid & 3) * 8;

    const int lane = tid & 31;
    const int wid = tid >> 5;
    const int warp_m = wid >> 1;
    const int warp_n = wid & 1;
    const int lrow = (lane & 7) + ((lane >> 3) & 1) * 8;
    const int lcol = (lane >> 4) * 8;

    const u32 base = (u32)__cvta_generic_to_shared(dsm);
    const u32 bA = base;
    const u32 bW = base + 2*STG_T;

    const __half* gA = A_ + za + (size_t)(m_base + a_row) * DMODEL + kbeg + a_col;
    const __half* gW = W_ + zw + (size_t)(n_base + a_row) * DMODEL + kbeg + a_col;
    float* Cz = C + (splitk ? 0 : za);

    const u32 aoff = (u32)((a_row * LDA + a_col) * 2);

    float acc[4][4];
    #pragma unroll
    for (int ni = 0; ni < 4; ni++) {
        #pragma unroll
        for (int t = 0; t < 4; t++) {
            acc[ni][t] = 0.0f;
        }
    }

    {
        cp16(bA + aoff, gA);
        cp16(bW + aoff, gW);
        cp_commit();
    }

    for (int s = 0; s < nst; s++) {
        const u32 buf = (u32)(s & 1) * STG_T;

        if (s < nst - 1) {
            int k0 = (s + 1) * 32;
            u32 nb = (u32)((s + 1) & 1) * STG_T;
            cp16(bA + nb + aoff, gA + k0);
            cp16(bW + nb + aoff, gW + k0);
            cp_commit();
            asm volatile("cp.async.wait_group 1;");
        } else {
            asm volatile("cp.async.wait_group 0;");
        }
        __syncthreads();

        #pragma unroll
        for (int kb = 0; kb < 32; kb += 16) {
            u32 ah[4];
            u32 bh[4][2];
            {
                u32 off = buf + (u32)(((warp_m * 16 + lrow) * LDA + kb + lcol) * 2);
                ldsm4(ah, bA + off);
            }
            #pragma unroll
            for (int g2 = 0; g2 < 2; g2++) {
                u32 off = buf + (u32)(((warp_n * 32 + g2 * 16 + lrow) * LDA + kb + lcol) * 2);
                u32 r0[4];
                ldsm4(r0, bW + off);
                bh[g2*2][0]   = r0[0];
                bh[g2*2+1][0] = r0[1];
                bh[g2*2][1]   = r0[2];
                bh[g2*2+1][1] = r0[3];
            }
            #pragma unroll
            for (int ni = 0; ni < 4; ni++) {
                mma_fp16(acc[ni], ah, bh[ni]);
            }
        }
        __syncthreads();
    }

    const int qr = lane >> 2;
    const int qc = (lane & 3) * 2;
    {
        int m0 = m_base + warp_m * 16 + qr;
        #pragma unroll
        for (int ni = 0; ni < 4; ni++) {
            int n = n_base + warp_n * 32 + ni * 8 + qc;
            float b0 = 0.0f;
            float b1 = 0.0f;
            if (addbias) {
                b0 = bias[n];
                b1 = bias[n + 1];
            }
            if (splitk) {
                atomicAdd(Cz + (size_t)m0 * DMODEL + n,           acc[ni][0] + b0);
                atomicAdd(Cz + (size_t)m0 * DMODEL + n + 1,       acc[ni][1] + b1);
                atomicAdd(Cz + (size_t)(m0 + 8) * DMODEL + n,     acc[ni][2] + b0);
                atomicAdd(Cz + (size_t)(m0 + 8) * DMODEL + n + 1, acc[ni][3] + b1);
            } else {
                float2 v0 = make_float2(acc[ni][0] + b0, acc[ni][1] + b1);
                float2 v1 = make_float2(acc[ni][2] + b0, acc[ni][3] + b1);
                *(float2*)(Cz + (size_t)m0 * DMODEL + n) = v0;
                *(float2*)(Cz + (size_t)(m0 + 8) * DMODEL + n) = v1;
            }
        }
    }
}

// ---------------- windowed attention (scores + PV via fp16 MMA) ----------------
// Also zeroes the `out` buffer (4 MB) ahead of the split-K O-projection.
#define SMEM_ATTN 51520

__global__ void __launch_bounds__(256, 2) local_attn(
    const float* __restrict__ Q, const float* __restrict__ K,
    const float* __restrict__ V, float* __restrict__ attn_w,
    float* __restrict__ out_zero)
{
    extern __shared__ __align__(16) char smc[];
    __half* Qh = (__half*)(smc);
    __half* Ks = (__half*)(smc + 9216);
    float*  Pf = (float*)(smc);
    __half* Phalf = (__half*)(smc);
    __half* Vt = (__half*)(smc + 33792);
    float*  bias_s = (float*)(smc + 51200);

    const int h  = blockIdx.y;
    const int i0 = blockIdx.x * 64;
    const int tid = threadIdx.x;

    // zero out-buffer slice (SD floats / 256 blocks = 4096 floats = 1024 float4)
    {
        int blk = blockIdx.y * gridDim.x + blockIdx.x;
        float4* dst = (float4*)(out_zero + (size_t)blk * 4096);
        float4 z = make_float4(0.f, 0.f, 0.f, 0.f);
        #pragma unroll
        for (int t = 0; t < 4; t++) {
            dst[tid + t * 256] = z;
        }
    }

    if (tid <= WIN) {
        bias_s[tid] = 0.1f * expf(-0.1f * (float)(WIN - tid));
    }

    for (int idx = tid; idx < 64 * 64; idx += 256) {
        int qi = idx >> 6;
        int d  = idx & 63;
        Qh[qi * QH_STR + d] = __float2half(Q[(size_t)(i0 + qi) * DMODEL + h * DKH + d]);
    }
    for (int idx = tid; idx < 128 * 64; idx += 256) {
        int kk = idx >> 6;
        int d  = idx & 63;
        int j = i0 - 64 + kk;
        int jc = (j < 0) ? 0 : j;
        Ks[kk * QH_STR + d] = __float2half(K[(size_t)jc * DMODEL + h * DKH + d]);
        Vt[d * VT_STR + kk] = __float2half(V[(size_t)jc * DMODEL + h * DKH + d]);
    }
    __syncthreads();

    const int lane = tid & 31;
    const int wid  = tid >> 5;
    const int warp_m = wid >> 1;
    const int warp_n = wid & 1;
    const int lrow = (lane & 7) + ((lane >> 3) & 1) * 8;
    const int lcol = (lane >> 4) * 8;

    const u32 bQh = (u32)__cvta_generic_to_shared(Qh);
    const u32 bKs = (u32)__cvta_generic_to_shared(Ks);
    const u32 bPf = (u32)__cvta_generic_to_shared(Pf);
    const u32 bVt = (u32)__cvta_generic_to_shared(Vt);

    float sc[8][4];
    #pragma unroll
    for (int nt = 0; nt < 8; nt++) {
        #pragma unroll
        for (int t = 0; t < 4; t++) {
            sc[nt][t] = 0.0f;
        }
    }
    #pragma unroll
    for (int kc = 0; kc < 64; kc += 16) {
        u32 ah[4];
        u32 bf[8][2];
        {
            u32 off = (u32)(((warp_m * 16 + lrow) * QH_STR + kc + lcol) * 2);
            ldsm4(ah, bQh + off);
        }
        #pragma unroll
        for (int g = 0; g < 4; g++) {
            u32 off = (u32)(((warp_n * 64 + g * 16 + lrow) * QH_STR + kc + lcol) * 2);
            u32 r0[4];
            ldsm4(r0, bKs + off);
            bf[g*2][0]   = r0[0];
            bf[g*2+1][0] = r0[1];
            bf[g*2][1]   = r0[2];
            bf[g*2+1][1] = r0[3];
        }
        #pragma unroll
        for (int nt = 0; nt < 8; nt++) {
            mma_fp16(sc[nt], ah, bf[nt]);
        }
    }
    __syncthreads();

    {
        const int qr = lane >> 2;
        const int qc = (lane & 3) * 2;
        #pragma unroll
        for (int nt = 0; nt < 8; nt++) {
            #pragma unroll
            for (int t = 0; t < 4; t++) {
                int kk = warp_n * 64 + nt * 8 + qc + (t & 1);
                int qi = warp_m * 16 + qr + (t >> 1) * 8;
                int r  = kk - qi;
                int jg = i0 - 64 + kk;
                float val = NEGV;
                if (r >= 0 && r <= WIN && jg >= 0) {
                    val = sc[nt][t] * 0.125f + bias_s[r];
                }
                Pf[qi * PA_STR + kk] = val;
            }
        }
    }
    __syncthreads();

    {
        for (int rr = 0; rr < 8; rr++) {
            int qi = wid * 8 + rr;
            float4 v4 = *(const float4*)&Pf[qi * PA_STR + lane * 4];
            float v[4] = {v4.x, v4.y, v4.z, v4.w};
            float mx = fmaxf(fmaxf(v[0], v[1]), fmaxf(v[2], v[3]));
            #pragma unroll
            for (int o = 16; o > 0; o >>= 1) {
                mx = fmaxf(mx, __shfl_xor_sync(0xffffffffu, mx, o));
            }
            float sum = 0.0f;
            #pragma unroll
            for (int t = 0; t < 4; t++) {
                v[t] = expf(v[t] - mx);
                sum += v[t];
            }
            #pragma unroll
            for (int o = 16; o > 0; o >>= 1) {
                sum += __shfl_xor_sync(0xffffffffu, sum, o);
            }
            float inv = 1.0f / sum;
            __half hh[4];
            __half ll[4];
            #pragma unroll
            for (int t = 0; t < 4; t++) {
                float p = v[t] * inv;
                hh[t] = __float2half(p);
                ll[t] = __float2half(p - __half2float(hh[t]));
            }
            __half* rowh = Phalf + qi * (PA_STR * 2);
            *(__half2*)(rowh + lane * 4)       = __halves2half2(hh[0], hh[1]);
            *(__half2*)(rowh + lane * 4 + 2)   = __halves2half2(hh[2], hh[3]);
            *(__half2*)(rowh + 128 + lane * 4)     = __halves2half2(ll[0], ll[1]);
            *(__half2*)(rowh + 128 + lane * 4 + 2) = __halves2half2(ll[2], ll[3]);
        }
    }
    __syncthreads();

    for (int idx = tid; idx < 64 * 128; idx += 256) {
        int qi = idx >> 7;
        int slot = idx & 127;
        int i = i0 + qi;
        float val = 0.0f;
        const __half* rowh = Phalf + qi * (PA_STR * 2);
        if (i < WIN) {
            if (slot <= qi) {
                int kk = slot + 64;
                val = __half2float(rowh[kk]) + __half2float(rowh[128 + kk]);
            }
        } else if (i >= S - WIN) {
            if (slot <= WIN) {
                int kk = qi + slot;
                val = __half2float(rowh[kk]) + __half2float(rowh[128 + kk]);
            }
        }
        attn_w[((size_t)h * S + i) * 128 + slot] = val;
    }

    float acc[4][4];
    #pragma unroll
    for (int ni = 0; ni < 4; ni++) {
        #pragma unroll
        for (int t = 0; t < 4; t++) {
            acc[ni][t] = 0.0f;
        }
    }
    #pragma unroll
    for (int kc = 0; kc < 128; kc += 16) {
        u32 ah[4];
        u32 bf[4][2];
        {
            u32 off = bPf + (u32)(((warp_m * 16 + lrow) * (PA_STR * 2) + kc + lcol) * 2);
            ldsm4(ah, off);
        }
        #pragma unroll
        for (int g = 0; g < 2; g++) {
            u32 off = bVt + (u32)(((warp_n * 32 + g * 16 + lrow) * VT_STR + kc + lcol) * 2);
            u32 r0[4];
            ldsm4(r0, off);
            bf[g*2][0]   = r0[0];
            bf[g*2+1][0] = r0[1];
            bf[g*2][1]   = r0[2];
            bf[g*2+1][1] = r0[3];
        }
        #pragma unroll
        for (int ni = 0; ni < 4; ni++) {
            mma_fp16(acc[ni], ah, bf[ni]);
        }
    }

    {
        const int qr = lane >> 2;
        const int qc = (lane & 3) * 2;
        #pragma unroll
        for (int ni = 0; ni < 4; ni++) {
            int dk = warp_n * 32 + ni * 8 + qc;
            #pragma unroll
            for (int half_m = 0; half_m < 2; half_m++) {
                int qi = warp_m * 16 + qr + half_m * 8;
                size_t base = (size_t)(i0 + qi) * DMODEL + h * DKH + dk;
                *(__half2*)(g_AOh + base) = __halves2half2(
                    __float2half(acc[ni][half_m * 2]),
                    __float2half(acc[ni][half_m * 2 + 1]));
            }
        }
    }
}

// ---------------- launch ----------------
extern "C" void kernel_launch(void* const* d_in, const int* in_sizes, int n_in,
                              void* d_out, int out_size) {
    const float* q  = (const float*)d_in[0];
    const float* k  = (const float*)d_in[1];
    const float* v  = (const float*)d_in[2];
    const float* Wq = (const float*)d_in[3];
    const float* Wk = (const float*)d_in[4];
    const float* Wv = (const float*)d_in[5];
    const float* Wo = (const float*)d_in[6];
    const float* bo = (const float*)d_in[7];

    float* out    = (float*)d_out;
    float* attn_w = out + (size_t)SD;

    __half* pxh;
    __half* pwh;
    __half* paoh;
    float* pqkv;
    cudaGetSymbolAddress((void**)&pxh,  g_xh);
    cudaGetSymbolAddress((void**)&pwh,  g_Wh);
    cudaGetSymbolAddress((void**)&pqkv, g_QKV);
    cudaGetSymbolAddress((void**)&paoh, g_AOh);

    cudaFuncSetAttribute(local_attn, cudaFuncAttributeMaxDynamicSharedMemorySize, SMEM_ATTN);
    cudaFuncSetAttribute(gemm64x64, cudaFuncAttributeMaxDynamicSharedMemorySize, SMEM_GEMM);

    convert_fp16<<<4096, 256>>>(q, k, v, Wq, Wk, Wv, Wo);

    gemm64x64<<<dim3(DMODEL/64, S/64, 3), 256, SMEM_GEMM>>>(
        pxh, pwh, pqkv, nullptr, 0);

    local_attn<<<dim3(S/64, NH), 256, SMEM_ATTN>>>(
        pqkv, pqkv + SD, pqkv + 2*SD, attn_w, out);

    gemm64x64<<<dim3(DMODEL/64, S/64, 2), 256, SMEM_GEMM>>>(
        paoh, pwh + 3*DD, out, bo, 1);
}

// round 16
// speedup vs baseline: 1.1179x; 1.1179x over previous
#include <cuda_runtime.h>
#include <cuda_fp16.h>
#include <cstdint>
#include <math.h>

#define S 2048
#define DMODEL 512
#define NH 8
#define DKH 64
#define WIN 64
#define NEGV -1000000000.0f
#define SD (S*DMODEL)
#define DD (DMODEL*DMODEL)

#define QH_STR 72     // halves per Q/K smem row
#define PA_STR 132    // fp32 words per P row (264 halves)
#define VT_STR 136    // halves per Vt row

#define LDA 40

typedef unsigned int u32;

// ---------------- device scratch (allocation-free rule) ----------------
__device__ __half g_xh[3*SD];     // activations fp16
__device__ __half g_Wh[4*DD];     // weights fp16
__device__ float  g_QKV[3*SD];
__device__ __half g_AOh[SD];      // attention output fp16

// ---------------- fp32 -> fp16 convert ----------------
__global__ void __launch_bounds__(256) convert_fp16(
    const float* __restrict__ q, const float* __restrict__ k, const float* __restrict__ v,
    const float* __restrict__ Wq, const float* __restrict__ Wk,
    const float* __restrict__ Wv, const float* __restrict__ Wo)
{
    const int SD4 = SD/4;
    const int DD4 = DD/4;
    int idx = blockIdx.x * 256 + threadIdx.x;
    const float* src;
    __half* dh;
    if (idx < 3*SD4) {
        int r = idx / SD4;
        size_t e = (size_t)(idx - r*SD4) * 4;
        src = (r == 0 ? q : (r == 1 ? k : v)) + e;
        dh = g_xh + (size_t)r*SD + e;
    } else {
        int j = idx - 3*SD4;
        int r = j / DD4;
        size_t e = (size_t)(j - r*DD4) * 4;
        src = (r == 0 ? Wq : (r == 1 ? Wk : (r == 2 ? Wv : Wo))) + e;
        dh = g_Wh + (size_t)r*DD + e;
    }
    float4 f = *(const float4*)src;
    *(__half2*)(dh)     = __halves2half2(__float2half(f.x), __float2half(f.y));
    *(__half2*)(dh + 2) = __halves2half2(__float2half(f.z), __float2half(f.w));
}

// ---------------- tensor-core helpers ----------------
__device__ __forceinline__ void ldsm4(u32* r, u32 a) {
    asm volatile("ldmatrix.sync.aligned.m8n8.x4.shared.b16 {%0,%1,%2,%3}, [%4];"
        : "=r"(r[0]), "=r"(r[1]), "=r"(r[2]), "=r"(r[3]) : "r"(a));
}
__device__ __forceinline__ void mma_fp16(float* c, const u32* a, const u32* b) {
    asm volatile("mma.sync.aligned.m16n8k16.row.col.f32.f16.f16.f32 "
        "{%0,%1,%2,%3},{%4,%5,%6,%7},{%8,%9},{%0,%1,%2,%3};"
        : "+f"(c[0]), "+f"(c[1]), "+f"(c[2]), "+f"(c[3])
        : "r"(a[0]), "r"(a[1]), "r"(a[2]), "r"(a[3]), "r"(b[0]), "r"(b[1]));
}
__device__ __forceinline__ void cp16(u32 dst, const void* src) {
    asm volatile("cp.async.cg.shared.global [%0], [%1], 16;" :: "r"(dst), "l"(src));
}
__device__ __forceinline__ void cp_commit() {
    asm volatile("cp.async.commit_group;");
}

// ---------------- GEMM: C = A @ W^T (+bias), plain fp16, 64x64 tile ----------------
// 4-stage cp.async ring, wait_group 2 in steady state (2 loads in flight).
#define STG_T (64*LDA*2)
#define NSTAGE 4
#define SMEM_GEMM (NSTAGE*2*STG_T)

__global__ void __launch_bounds__(256, 4) gemm64x64(
    const __half* __restrict__ A_, const __half* __restrict__ W_,
    float* __restrict__ C, const float* __restrict__ bias)
{
    extern __shared__ __align__(16) __half dsm[];

    const size_t za = (size_t)blockIdx.z * SD;
    const size_t zw = (size_t)blockIdx.z * DD;
    const int tid = threadIdx.x;
    const int m_base = blockIdx.y * 64;
    const int n_base = blockIdx.x * 64;

    const int a_row = tid >> 2;
    const int a_col = (tid & 3) * 8;

    const int lane = tid & 31;
    const int wid = tid >> 5;
    const int warp_m = wid >> 1;
    const int warp_n = wid & 1;
    const int lrow = (lane & 7) + ((lane >> 3) & 1) * 8;
    const int lcol = (lane >> 4) * 8;

    const u32 base = (u32)__cvta_generic_to_shared(dsm);
    const u32 bA = base;
    const u32 bW = base + NSTAGE*STG_T;

    const __half* gA = A_ + za + (size_t)(m_base + a_row) * DMODEL + a_col;
    const __half* gW = W_ + zw + (size_t)(n_base + a_row) * DMODEL + a_col;
    float* Cz = C + za;

    const u32 aoff = (u32)((a_row * LDA + a_col) * 2);

    float acc[4][4];
    #pragma unroll
    for (int ni = 0; ni < 4; ni++) {
        #pragma unroll
        for (int t = 0; t < 4; t++) {
            acc[ni][t] = 0.0f;
        }
    }

    // prologue: stages 0,1,2 (one commit group each)
    #pragma unroll
    for (int p = 0; p < NSTAGE - 1; p++) {
        u32 sb = (u32)p * STG_T;
        cp16(bA + sb + aoff, gA + p * 32);
        cp16(bW + sb + aoff, gW + p * 32);
        cp_commit();
    }

    const int nst = 16;
    for (int s = 0; s < nst; s++) {
        // wait for group s: pending allowed = min(2, nst-1-s)
        if (s <= nst - 3) {
            asm volatile("cp.async.wait_group 2;");
        } else if (s == nst - 2) {
            asm volatile("cp.async.wait_group 1;");
        } else {
            asm volatile("cp.async.wait_group 0;");
        }
        __syncthreads();

        // issue stage s+3 into buffer (s+3)%4 == (s-1)%4 (safe: post-sync)
        if (s < nst - (NSTAGE - 1)) {
            int k0 = (s + NSTAGE - 1) * 32;
            u32 nb = (u32)((s + NSTAGE - 1) % NSTAGE) * STG_T;
            cp16(bA + nb + aoff, gA + k0);
            cp16(bW + nb + aoff, gW + k0);
            cp_commit();
        }

        const u32 buf = (u32)(s % NSTAGE) * STG_T;

        #pragma unroll
        for (int kb = 0; kb < 32; kb += 16) {
            u32 ah[4];
            u32 bh[4][2];
            {
                u32 off = buf + (u32)(((warp_m * 16 + lrow) * LDA + kb + lcol) * 2);
                ldsm4(ah, bA + off);
            }
            #pragma unroll
            for (int g2 = 0; g2 < 2; g2++) {
                u32 off = buf + (u32)(((warp_n * 32 + g2 * 16 + lrow) * LDA + kb + lcol) * 2);
                u32 r0[4];
                ldsm4(r0, bW + off);
                bh[g2*2][0]   = r0[0];
                bh[g2*2+1][0] = r0[1];
                bh[g2*2][1]   = r0[2];
                bh[g2*2+1][1] = r0[3];
            }
            #pragma unroll
            for (int ni = 0; ni < 4; ni++) {
                mma_fp16(acc[ni], ah, bh[ni]);
            }
        }
    }

    const int qr = lane >> 2;
    const int qc = (lane & 3) * 2;
    {
        int m0 = m_base + warp_m * 16 + qr;
        #pragma unroll
        for (int ni = 0; ni < 4; ni++) {
            int n = n_base + warp_n * 32 + ni * 8 + qc;
            float b0 = 0.0f;
            float b1 = 0.0f;
            if (bias) {
                b0 = bias[n];
                b1 = bias[n + 1];
            }
            float2 v0 = make_float2(acc[ni][0] + b0, acc[ni][1] + b1);
            float2 v1 = make_float2(acc[ni][2] + b0, acc[ni][3] + b1);
            *(float2*)(Cz + (size_t)m0 * DMODEL + n) = v0;
            *(float2*)(Cz + (size_t)(m0 + 8) * DMODEL + n) = v1;
        }
    }
}

// ---------------- windowed attention (scores + PV via fp16 MMA) ----------------
#define SMEM_ATTN 51520

__global__ void __launch_bounds__(256, 2) local_attn(
    const float* __restrict__ Q, const float* __restrict__ K,
    const float* __restrict__ V, float* __restrict__ attn_w)
{
    extern __shared__ __align__(16) char smc[];
    __half* Qh = (__half*)(smc);
    __half* Ks = (__half*)(smc + 9216);
    float*  Pf = (float*)(smc);
    __half* Phalf = (__half*)(smc);
    __half* Vt = (__half*)(smc + 33792);
    float*  bias_s = (float*)(smc + 51200);

    const int h  = blockIdx.y;
    const int i0 = blockIdx.x * 64;
    const int tid = threadIdx.x;

    if (tid <= WIN) {
        bias_s[tid] = 0.1f * expf(-0.1f * (float)(WIN - tid));
    }

    for (int idx = tid; idx < 64 * 64; idx += 256) {
        int qi = idx >> 6;
        int d  = idx & 63;
        Qh[qi * QH_STR + d] = __float2half(Q[(size_t)(i0 + qi) * DMODEL + h * DKH + d]);
    }
    for (int idx = tid; idx < 128 * 64; idx += 256) {
        int kk = idx >> 6;
        int d  = idx & 63;
        int j = i0 - 64 + kk;
        int jc = (j < 0) ? 0 : j;
        Ks[kk * QH_STR + d] = __float2half(K[(size_t)jc * DMODEL + h * DKH + d]);
        Vt[d * VT_STR + kk] = __float2half(V[(size_t)jc * DMODEL + h * DKH + d]);
    }
    __syncthreads();

    const int lane = tid & 31;
    const int wid  = tid >> 5;
    const int warp_m = wid >> 1;
    const int warp_n = wid & 1;
    const int lrow = (lane & 7) + ((lane >> 3) & 1) * 8;
    const int lcol = (lane >> 4) * 8;

    const u32 bQh = (u32)__cvta_generic_to_shared(Qh);
    const u32 bKs = (u32)__cvta_generic_to_shared(Ks);
    const u32 bPf = (u32)__cvta_generic_to_shared(Pf);
    const u32 bVt = (u32)__cvta_generic_to_shared(Vt);

    float sc[8][4];
    #pragma unroll
    for (int nt = 0; nt < 8; nt++) {
        #pragma unroll
        for (int t = 0; t < 4; t++) {
            sc[nt][t] = 0.0f;
        }
    }
    #pragma unroll
    for (int kc = 0; kc < 64; kc += 16) {
        u32 ah[4];
        u32 bf[8][2];
        {
            u32 off = (u32)(((warp_m * 16 + lrow) * QH_STR + kc + lcol) * 2);
            ldsm4(ah, bQh + off);
        }
        #pragma unroll
        for (int g = 0; g < 4; g++) {
            u32 off = (u32)(((warp_n * 64 + g * 16 + lrow) * QH_STR + kc + lcol) * 2);
            u32 r0[4];
            ldsm4(r0, bKs + off);
            bf[g*2][0]   = r0[0];
            bf[g*2+1][0] = r0[1];
            bf[g*2][1]   = r0[2];
            bf[g*2+1][1] = r0[3];
        }
        #pragma unroll
        for (int nt = 0; nt < 8; nt++) {
            mma_fp16(sc[nt], ah, bf[nt]);
        }
    }
    __syncthreads();

    {
        const int qr = lane >> 2;
        const int qc = (lane & 3) * 2;
        #pragma unroll
        for (int nt = 0; nt < 8; nt++) {
            #pragma unroll
            for (int t = 0; t < 4; t++) {
                int kk = warp_n * 64 + nt * 8 + qc + (t & 1);
                int qi = warp_m * 16 + qr + (t >> 1) * 8;
                int r  = kk - qi;
                int jg = i0 - 64 + kk;
                float val = NEGV;
                if (r >= 0 && r <= WIN && jg >= 0) {
                    val = sc[nt][t] * 0.125f + bias_s[r];
                }
                Pf[qi * PA_STR + kk] = val;
            }
        }
    }
    __syncthreads();

    {
        for (int rr = 0; rr < 8; rr++) {
            int qi = wid * 8 + rr;
            float4 v4 = *(const float4*)&Pf[qi * PA_STR + lane * 4];
            float v[4] = {v4.x, v4.y, v4.z, v4.w};
            float mx = fmaxf(fmaxf(v[0], v[1]), fmaxf(v[2], v[3]));
            #pragma unroll
            for (int o = 16; o > 0; o >>= 1) {
                mx = fmaxf(mx, __shfl_xor_sync(0xffffffffu, mx, o));
            }
            float sum = 0.0f;
            #pragma unroll
            for (int t = 0; t < 4; t++) {
                v[t] = expf(v[t] - mx);
                sum += v[t];
            }
            #pragma unroll
            for (int o = 16; o > 0; o >>= 1) {
                sum += __shfl_xor_sync(0xffffffffu, sum, o);
            }
            float inv = 1.0f / sum;
            __half hh[4];
            __half ll[4];
            #pragma unroll
            for (int t = 0; t < 4; t++) {
                float p = v[t] * inv;
                hh[t] = __float2half(p);
                ll[t] = __float2half(p - __half2float(hh[t]));
            }
            __half* rowh = Phalf + qi * (PA_STR * 2);
            *(__half2*)(rowh + lane * 4)       = __halves2half2(hh[0], hh[1]);
            *(__half2*)(rowh + lane * 4 + 2)   = __halves2half2(hh[2], hh[3]);
            *(__half2*)(rowh + 128 + lane * 4)     = __halves2half2(ll[0], ll[1]);
            *(__half2*)(rowh + 128 + lane * 4 + 2) = __halves2half2(ll[2], ll[3]);
        }
    }
    __syncthreads();

    for (int idx = tid; idx < 64 * 128; idx += 256) {
        int qi = idx >> 7;
        int slot = idx & 127;
        int i = i0 + qi;
        float val = 0.0f;
        const __half* rowh = Phalf + qi * (PA_STR * 2);
        if (i < WIN) {
            if (slot <= qi) {
                int kk = slot + 64;
                val = __half2float(rowh[kk]) + __half2float(rowh[128 + kk]);
            }
        } else if (i >= S - WIN) {
            if (slot <= WIN) {
                int kk = qi + slot;
                val = __half2float(rowh[kk]) + __half2float(rowh[128 + kk]);
            }
        }
        attn_w[((size_t)h * S + i) * 128 + slot] = val;
    }

    float acc[4][4];
    #pragma unroll
    for (int ni = 0; ni < 4; ni++) {
        #pragma unroll
        for (int t = 0; t < 4; t++) {
            acc[ni][t] = 0.0f;
        }
    }
    #pragma unroll
    for (int kc = 0; kc < 128; kc += 16) {
        u32 ah[4];
        u32 bf[4][2];
        {
            u32 off = bPf + (u32)(((warp_m * 16 + lrow) * (PA_STR * 2) + kc + lcol) * 2);
            ldsm4(ah, off);
        }
        #pragma unroll
        for (int g = 0; g < 2; g++) {
            u32 off = bVt + (u32)(((warp_n * 32 + g * 16 + lrow) * VT_STR + kc + lcol) * 2);
            u32 r0[4];
            ldsm4(r0, off);
            bf[g*2][0]   = r0[0];
            bf[g*2+1][0] = r0[1];
            bf[g*2][1]   = r0[2];
            bf[g*2+1][1] = r0[3];
        }
        #pragma unroll
        for (int ni = 0; ni < 4; ni++) {
            mma_fp16(acc[ni], ah, bf[ni]);
        }
    }

    {
        const int qr = lane >> 2;
        const int qc = (lane & 3) * 2;
        #pragma unroll
        for (int ni = 0; ni < 4; ni++) {
            int dk = warp_n * 32 + ni * 8 + qc;
            #pragma unroll
            for (int half_m = 0; half_m < 2; half_m++) {
                int qi = warp_m * 16 + qr + half_m * 8;
                size_t base = (size_t)(i0 + qi) * DMODEL + h * DKH + dk;
                *(__half2*)(g_AOh + base) = __halves2half2(
                    __float2half(acc[ni][half_m * 2]),
                    __float2half(acc[ni][half_m * 2 + 1]));
            }
        }
    }
}

// ---------------- launch ----------------
extern "C" void kernel_launch(void* const* d_in, const int* in_sizes, int n_in,
                              void* d_out, int out_size) {
    const float* q  = (const float*)d_in[0];
    const float* k  = (const float*)d_in[1];
    const float* v  = (const float*)d_in[2];
    const float* Wq = (const float*)d_in[3];
    const float* Wk = (const float*)d_in[4];
    const float* Wv = (const float*)d_in[5];
    const float* Wo = (const float*)d_in[6];
    const float* bo = (const float*)d_in[7];

    float* out    = (float*)d_out;
    float* attn_w = out + (size_t)SD;

    __half* pxh;
    __half* pwh;
    __half* paoh;
    float* pqkv;
    cudaGetSymbolAddress((void**)&pxh,  g_xh);
    cudaGetSymbolAddress((void**)&pwh,  g_Wh);
    cudaGetSymbolAddress((void**)&pqkv, g_QKV);
    cudaGetSymbolAddress((void**)&paoh, g_AOh);

    cudaFuncSetAttribute(local_attn, cudaFuncAttributeMaxDynamicSharedMemorySize, SMEM_ATTN);
    cudaFuncSetAttribute(gemm64x64, cudaFuncAttributeMaxDynamicSharedMemorySize, SMEM_GEMM);

    convert_fp16<<<4096, 256>>>(q, k, v, Wq, Wk, Wv, Wo);

    gemm64x64<<<dim3(DMODEL/64, S/64, 3), 256, SMEM_GEMM>>>(
        pxh, pwh, pqkv, nullptr);

    local_attn<<<dim3(S/64, NH), 256, SMEM_ATTN>>>(pqkv, pqkv + SD, pqkv + 2*SD, attn_w);

    gemm64x64<<<dim3(DMODEL/64, S/64, 1), 256, SMEM_GEMM>>>(
        paoh, pwh + 3*DD, out, bo);
}

// round 17
// speedup vs baseline: 1.1244x; 1.0058x over previous
#include <cuda_runtime.h>
#include <cuda_fp16.h>
#include <cstdint>
#include <math.h>

#define S 2048
#define DMODEL 512
#define NH 8
#define DKH 64
#define WIN 64
#define NEGV -1000000000.0f
#define SD (S*DMODEL)
#define DD (DMODEL*DMODEL)

#define QH_STR 72     // halves per Q/K smem row
#define PA_STR 132    // fp32 words per P row (264 halves)
#define VT_STR 136    // halves per Vt row

#define LDA 40

typedef unsigned int u32;

// ---------------- device scratch (allocation-free rule) ----------------
__device__ __half g_xh[3*SD];     // activations fp16
__device__ __half g_Wh[4*DD];     // weights fp16
__device__ float  g_QKV[3*SD];
__device__ __half g_AOh[SD];      // attention output fp16

// ---------------- fp32 -> fp16 convert ----------------
__global__ void __launch_bounds__(256) convert_fp16(
    const float* __restrict__ q, const float* __restrict__ k, const float* __restrict__ v,
    const float* __restrict__ Wq, const float* __restrict__ Wk,
    const float* __restrict__ Wv, const float* __restrict__ Wo)
{
    const int SD4 = SD/4;
    const int DD4 = DD/4;
    int idx = blockIdx.x * 256 + threadIdx.x;
    const float* src;
    __half* dh;
    if (idx < 3*SD4) {
        int r = idx / SD4;
        size_t e = (size_t)(idx - r*SD4) * 4;
        src = (r == 0 ? q : (r == 1 ? k : v)) + e;
        dh = g_xh + (size_t)r*SD + e;
    } else {
        int j = idx - 3*SD4;
        int r = j / DD4;
        size_t e = (size_t)(j - r*DD4) * 4;
        src = (r == 0 ? Wq : (r == 1 ? Wk : (r == 2 ? Wv : Wo))) + e;
        dh = g_Wh + (size_t)r*DD + e;
    }
    float4 f = *(const float4*)src;
    *(__half2*)(dh)     = __halves2half2(__float2half(f.x), __float2half(f.y));
    *(__half2*)(dh + 2) = __halves2half2(__float2half(f.z), __float2half(f.w));
}

// ---------------- tensor-core helpers ----------------
__device__ __forceinline__ void ldsm4(u32* r, u32 a) {
    asm volatile("ldmatrix.sync.aligned.m8n8.x4.shared.b16 {%0,%1,%2,%3}, [%4];"
        : "=r"(r[0]), "=r"(r[1]), "=r"(r[2]), "=r"(r[3]) : "r"(a));
}
__device__ __forceinline__ void mma_fp16(float* c, const u32* a, const u32* b) {
    asm volatile("mma.sync.aligned.m16n8k16.row.col.f32.f16.f16.f32 "
        "{%0,%1,%2,%3},{%4,%5,%6,%7},{%8,%9},{%0,%1,%2,%3};"
        : "+f"(c[0]), "+f"(c[1]), "+f"(c[2]), "+f"(c[3])
        : "r"(a[0]), "r"(a[1]), "r"(a[2]), "r"(a[3]), "r"(b[0]), "r"(b[1]));
}
__device__ __forceinline__ void cp16(u32 dst, const void* src) {
    asm volatile("cp.async.cg.shared.global [%0], [%1], 16;" :: "r"(dst), "l"(src));
}
__device__ __forceinline__ void cp_commit() {
    asm volatile("cp.async.commit_group;");
}

// ---------------- GEMM: C = A @ W^T (+bias), plain fp16, 64x64 tile ----------------
// 5-stage cp.async ring, wait_group 3 in steady state (3 loads in flight).
#define STG_T (64*LDA*2)
#define NSTAGE 5
#define SMEM_GEMM (NSTAGE*2*STG_T)

__global__ void __launch_bounds__(256, 4) gemm64x64(
    const __half* __restrict__ A_, const __half* __restrict__ W_,
    float* __restrict__ C, const float* __restrict__ bias)
{
    extern __shared__ __align__(16) __half dsm[];

    const size_t za = (size_t)blockIdx.z * SD;
    const size_t zw = (size_t)blockIdx.z * DD;
    const int tid = threadIdx.x;
    const int m_base = blockIdx.y * 64;
    const int n_base = blockIdx.x * 64;

    const int a_row = tid >> 2;
    const int a_col = (tid & 3) * 8;

    const int lane = tid & 31;
    const int wid = tid >> 5;
    const int warp_m = wid >> 1;
    const int warp_n = wid & 1;
    const int lrow = (lane & 7) + ((lane >> 3) & 1) * 8;
    const int lcol = (lane >> 4) * 8;

    const u32 base = (u32)__cvta_generic_to_shared(dsm);
    const u32 bA = base;
    const u32 bW = base + NSTAGE*STG_T;

    const __half* gA = A_ + za + (size_t)(m_base + a_row) * DMODEL + a_col;
    const __half* gW = W_ + zw + (size_t)(n_base + a_row) * DMODEL + a_col;
    float* Cz = C + za;

    const u32 aoff = (u32)((a_row * LDA + a_col) * 2);

    float acc[4][4];
    #pragma unroll
    for (int ni = 0; ni < 4; ni++) {
        #pragma unroll
        for (int t = 0; t < 4; t++) {
            acc[ni][t] = 0.0f;
        }
    }

    // prologue: stages 0..3 (one commit group each)
    #pragma unroll
    for (int p = 0; p < NSTAGE - 1; p++) {
        u32 sb = (u32)p * STG_T;
        cp16(bA + sb + aoff, gA + p * 32);
        cp16(bW + sb + aoff, gW + p * 32);
        cp_commit();
    }

    const int nst = 16;
    for (int s = 0; s < nst; s++) {
        // wait for group s: pending allowed = min(NSTAGE-2, nst-1-s)
        int rem = nst - 1 - s;
        if (rem >= 3) {
            asm volatile("cp.async.wait_group 3;");
        } else if (rem == 2) {
            asm volatile("cp.async.wait_group 2;");
        } else if (rem == 1) {
            asm volatile("cp.async.wait_group 1;");
        } else {
            asm volatile("cp.async.wait_group 0;");
        }
        __syncthreads();

        // issue stage s+4 into buffer (s+4)%5 == (s-1)%5 (safe: post-sync)
        if (s < nst - (NSTAGE - 1)) {
            int k0 = (s + NSTAGE - 1) * 32;
            u32 nb = (u32)((s + NSTAGE - 1) % NSTAGE) * STG_T;
            cp16(bA + nb + aoff, gA + k0);
            cp16(bW + nb + aoff, gW + k0);
            cp_commit();
        }

        const u32 buf = (u32)(s % NSTAGE) * STG_T;

        #pragma unroll
        for (int kb = 0; kb < 32; kb += 16) {
            u32 ah[4];
            u32 bh[4][2];
            {
                u32 off = buf + (u32)(((warp_m * 16 + lrow) * LDA + kb + lcol) * 2);
                ldsm4(ah, bA + off);
            }
            #pragma unroll
            for (int g2 = 0; g2 < 2; g2++) {
                u32 off = buf + (u32)(((warp_n * 32 + g2 * 16 + lrow) * LDA + kb + lcol) * 2);
                u32 r0[4];
                ldsm4(r0, bW + off);
                bh[g2*2][0]   = r0[0];
                bh[g2*2+1][0] = r0[1];
                bh[g2*2][1]   = r0[2];
                bh[g2*2+1][1] = r0[3];
            }
            #pragma unroll
            for (int ni = 0; ni < 4; ni++) {
                mma_fp16(acc[ni], ah, bh[ni]);
            }
        }
    }

    const int qr = lane >> 2;
    const int qc = (lane & 3) * 2;
    {
        int m0 = m_base + warp_m * 16 + qr;
        #pragma unroll
        for (int ni = 0; ni < 4; ni++) {
            int n = n_base + warp_n * 32 + ni * 8 + qc;
            float b0 = 0.0f;
            float b1 = 0.0f;
            if (bias) {
                b0 = bias[n];
                b1 = bias[n + 1];
            }
            float2 v0 = make_float2(acc[ni][0] + b0, acc[ni][1] + b1);
            float2 v1 = make_float2(acc[ni][2] + b0, acc[ni][3] + b1);
            *(float2*)(Cz + (size_t)m0 * DMODEL + n) = v0;
            *(float2*)(Cz + (size_t)(m0 + 8) * DMODEL + n) = v1;
        }
    }
}

// ---------------- windowed attention (scores + PV via fp16 MMA) ----------------
#define SMEM_ATTN 51520

__global__ void __launch_bounds__(256, 2) local_attn(
    const float* __restrict__ Q, const float* __restrict__ K,
    const float* __restrict__ V, float* __restrict__ attn_w)
{
    extern __shared__ __align__(16) char smc[];
    __half* Qh = (__half*)(smc);
    __half* Ks = (__half*)(smc + 9216);
    float*  Pf = (float*)(smc);
    __half* Phalf = (__half*)(smc);
    __half* Vt = (__half*)(smc + 33792);
    float*  bias_s = (float*)(smc + 51200);

    const int h  = blockIdx.y;
    const int i0 = blockIdx.x * 64;
    const int tid = threadIdx.x;

    if (tid <= WIN) {
        bias_s[tid] = 0.1f * expf(-0.1f * (float)(WIN - tid));
    }

    for (int idx = tid; idx < 64 * 64; idx += 256) {
        int qi = idx >> 6;
        int d  = idx & 63;
        Qh[qi * QH_STR + d] = __float2half(Q[(size_t)(i0 + qi) * DMODEL + h * DKH + d]);
    }
    for (int idx = tid; idx < 128 * 64; idx += 256) {
        int kk = idx >> 6;
        int d  = idx & 63;
        int j = i0 - 64 + kk;
        int jc = (j < 0) ? 0 : j;
        Ks[kk * QH_STR + d] = __float2half(K[(size_t)jc * DMODEL + h * DKH + d]);
        Vt[d * VT_STR + kk] = __float2half(V[(size_t)jc * DMODEL + h * DKH + d]);
    }
    __syncthreads();

    const int lane = tid & 31;
    const int wid  = tid >> 5;
    const int warp_m = wid >> 1;
    const int warp_n = wid & 1;
    const int lrow = (lane & 7) + ((lane >> 3) & 1) * 8;
    const int lcol = (lane >> 4) * 8;

    const u32 bQh = (u32)__cvta_generic_to_shared(Qh);
    const u32 bKs = (u32)__cvta_generic_to_shared(Ks);
    const u32 bPf = (u32)__cvta_generic_to_shared(Pf);
    const u32 bVt = (u32)__cvta_generic_to_shared(Vt);

    float sc[8][4];
    #pragma unroll
    for (int nt = 0; nt < 8; nt++) {
        #pragma unroll
        for (int t = 0; t < 4; t++) {
            sc[nt][t] = 0.0f;
        }
    }
    #pragma unroll
    for (int kc = 0; kc < 64; kc += 16) {
        u32 ah[4];
        u32 bf[8][2];
        {
            u32 off = (u32)(((warp_m * 16 + lrow) * QH_STR + kc + lcol) * 2);
            ldsm4(ah, bQh + off);
        }
        #pragma unroll
        for (int g = 0; g < 4; g++) {
            u32 off = (u32)(((warp_n * 64 + g * 16 + lrow) * QH_STR + kc + lcol) * 2);
            u32 r0[4];
            ldsm4(r0, bKs + off);
            bf[g*2][0]   = r0[0];
            bf[g*2+1][0] = r0[1];
            bf[g*2][1]   = r0[2];
            bf[g*2+1][1] = r0[3];
        }
        #pragma unroll
        for (int nt = 0; nt < 8; nt++) {
            mma_fp16(sc[nt], ah, bf[nt]);
        }
    }
    __syncthreads();

    {
        const int qr = lane >> 2;
        const int qc = (lane & 3) * 2;
        #pragma unroll
        for (int nt = 0; nt < 8; nt++) {
            #pragma unroll
            for (int t = 0; t < 4; t++) {
                int kk = warp_n * 64 + nt * 8 + qc + (t & 1);
                int qi = warp_m * 16 + qr + (t >> 1) * 8;
                int r  = kk - qi;
                int jg = i0 - 64 + kk;
                float val = NEGV;
                if (r >= 0 && r <= WIN && jg >= 0) {
                    val = sc[nt][t] * 0.125f + bias_s[r];
                }
                Pf[qi * PA_STR + kk] = val;
            }
        }
    }
    __syncthreads();

    {
        for (int rr = 0; rr < 8; rr++) {
            int qi = wid * 8 + rr;
            float4 v4 = *(const float4*)&Pf[qi * PA_STR + lane * 4];
            float v[4] = {v4.x, v4.y, v4.z, v4.w};
            float mx = fmaxf(fmaxf(v[0], v[1]), fmaxf(v[2], v[3]));
            #pragma unroll
            for (int o = 16; o > 0; o >>= 1) {
                mx = fmaxf(mx, __shfl_xor_sync(0xffffffffu, mx, o));
            }
            float sum = 0.0f;
            #pragma unroll
            for (int t = 0; t < 4; t++) {
                v[t] = expf(v[t] - mx);
                sum += v[t];
            }
            #pragma unroll
            for (int o = 16; o > 0; o >>= 1) {
                sum += __shfl_xor_sync(0xffffffffu, sum, o);
            }
            float inv = 1.0f / sum;
            __half hh[4];
            __half ll[4];
            #pragma unroll
            for (int t = 0; t < 4; t++) {
                float p = v[t] * inv;
                hh[t] = __float2half(p);
                ll[t] = __float2half(p - __half2float(hh[t]));
            }
            __half* rowh = Phalf + qi * (PA_STR * 2);
            *(__half2*)(rowh + lane * 4)       = __halves2half2(hh[0], hh[1]);
            *(__half2*)(rowh + lane * 4 + 2)   = __halves2half2(hh[2], hh[3]);
            *(__half2*)(rowh + 128 + lane * 4)     = __halves2half2(ll[0], ll[1]);
            *(__half2*)(rowh + 128 + lane * 4 + 2) = __halves2half2(ll[2], ll[3]);
        }
    }
    __syncthreads();

    for (int idx = tid; idx < 64 * 128; idx += 256) {
        int qi = idx >> 7;
        int slot = idx & 127;
        int i = i0 + qi;
        float val = 0.0f;
        const __half* rowh = Phalf + qi * (PA_STR * 2);
        if (i < WIN) {
            if (slot <= qi) {
                int kk = slot + 64;
                val = __half2float(rowh[kk]) + __half2float(rowh[128 + kk]);
            }
        } else if (i >= S - WIN) {
            if (slot <= WIN) {
                int kk = qi + slot;
                val = __half2float(rowh[kk]) + __half2float(rowh[128 + kk]);
            }
        }
        attn_w[((size_t)h * S + i) * 128 + slot] = val;
    }

    float acc[4][4];
    #pragma unroll
    for (int ni = 0; ni < 4; ni++) {
        #pragma unroll
        for (int t = 0; t < 4; t++) {
            acc[ni][t] = 0.0f;
        }
    }
    #pragma unroll
    for (int kc = 0; kc < 128; kc += 16) {
        u32 ah[4];
        u32 bf[4][2];
        {
            u32 off = bPf + (u32)(((warp_m * 16 + lrow) * (PA_STR * 2) + kc + lcol) * 2);
            ldsm4(ah, off);
        }
        #pragma unroll
        for (int g = 0; g < 2; g++) {
            u32 off = bVt + (u32)(((warp_n * 32 + g * 16 + lrow) * VT_STR + kc + lcol) * 2);
            u32 r0[4];
            ldsm4(r0, off);
            bf[g*2][0]   = r0[0];
            bf[g*2+1][0] = r0[1];
            bf[g*2][1]   = r0[2];
            bf[g*2+1][1] = r0[3];
        }
        #pragma unroll
        for (int ni = 0; ni < 4; ni++) {
            mma_fp16(acc[ni], ah, bf[ni]);
        }
    }

    {
        const int qr = lane >> 2;
        const int qc = (lane & 3) * 2;
        #pragma unroll
        for (int ni = 0; ni < 4; ni++) {
            int dk = warp_n * 32 + ni * 8 + qc;
            #pragma unroll
            for (int half_m = 0; half_m < 2; half_m++) {
                int qi = warp_m * 16 + qr + half_m * 8;
                size_t base = (size_t)(i0 + qi) * DMODEL + h * DKH + dk;
                *(__half2*)(g_AOh + base) = __halves2half2(
                    __float2half(acc[ni][half_m * 2]),
                    __float2half(acc[ni][half_m * 2 + 1]));
            }
        }
    }
}

// ---------------- launch ----------------
extern "C" void kernel_launch(void* const* d_in, const int* in_sizes, int n_in,
                              void* d_out, int out_size) {
    const float* q  = (const float*)d_in[0];
    const float* k  = (const float*)d_in[1];
    const float* v  = (const float*)d_in[2];
    const float* Wq = (const float*)d_in[3];
    const float* Wk = (const float*)d_in[4];
    const float* Wv = (const float*)d_in[5];
    const float* Wo = (const float*)d_in[6];
    const float* bo = (const float*)d_in[7];

    float* out    = (float*)d_out;
    float* attn_w = out + (size_t)SD;

    __half* pxh;
    __half* pwh;
    __half* paoh;
    float* pqkv;
    cudaGetSymbolAddress((void**)&pxh,  g_xh);
    cudaGetSymbolAddress((void**)&pwh,  g_Wh);
    cudaGetSymbolAddress((void**)&pqkv, g_QKV);
    cudaGetSymbolAddress((void**)&paoh, g_AOh);

    cudaFuncSetAttribute(local_attn, cudaFuncAttributeMaxDynamicSharedMemorySize, SMEM_ATTN);
    cudaFuncSetAttribute(gemm64x64, cudaFuncAttributeMaxDynamicSharedMemorySize, SMEM_GEMM);

    convert_fp16<<<4096, 256>>>(q, k, v, Wq, Wk, Wv, Wo);

    gemm64x64<<<dim3(DMODEL/64, S/64, 3), 256, SMEM_GEMM>>>(
        pxh, pwh, pqkv, nullptr);

    local_attn<<<dim3(S/64, NH), 256, SMEM_ATTN>>>(pqkv, pqkv + SD, pqkv + 2*SD, attn_w);

    gemm64x64<<<dim3(DMODEL/64, S/64, 1), 256, SMEM_GEMM>>>(
        paoh, pwh + 3*DD, out, bo);
}